// round 1
// baseline (speedup 1.0000x reference)
#include <cuda_runtime.h>

// ---------------------------------------------------------------------------
// krnn_conv_local1: conv1d -> GRU encoder -> GRU decoder -> linear, x9 configs,
// softmax-combined. BN=51200 independent sequences; each block handles 32
// sequences of one config. Warp = 4 sequences; thread owns hidden units
// (lane, lane+32) for its 4 sequences.
// ---------------------------------------------------------------------------

namespace {
constexpr int B_ = 64, N_ = 800, TIN = 15, FIN = 8, TOUT = 12, NCONF = 9;
constexpr int BN_ = B_ * N_;          // 51200
constexpr int SPB = 32;               // sequences per block
constexpr int NTHR = 256;             // 8 warps
}

// per-config outputs [NCONF][BN_][TOUT]
__device__ float g_scratch[(size_t)NCONF * BN_ * TOUT];

struct Smem {
  float2 whh2[64 * 96];   // [i][g*32+l] = (whh[g*64+l][i], whh[g*64+l+32][i])  48KB
  float2 wih2[8 * 96];    // [f][g*32+l] same packing for the 192x8 input matrix
  float2 h2[16 * 64];     // [warp*2 + pair][i] = (h_seqA[i], h_seqB[i])
  float  xs[SPB * 120];   // staged X slab (15*8 per seq)
  float  co[SPB * 112];   // conv output [seq][cout*14 + l]
  float  cw[256];         // conv weights [cout][cin][K]
  float  cb[8];
  float  lw[64];
};

__device__ __forceinline__ float sigf(float x) {
  return __fdividef(1.0f, 1.0f + __expf(-x));
}
__device__ __forceinline__ float tanhf_(float x) {
  return 1.0f - __fdividef(2.0f, __expf(2.0f * x) + 1.0f);
}

// 24-FMA gh inner-loop body (4 seqs x 6 gate-rows), shared by enc and dec.
#define GH_LOOP(hp, wb)                                                        \
  _Pragma("unroll 4")                                                          \
  for (int i = 0; i < 64; ++i) {                                               \
    float2 ha = (hp)[i];                                                       \
    float2 hb = (hp)[64 + i];                                                  \
    float2 wr = (wb)[i * 96];                                                  \
    float2 wz = (wb)[i * 96 + 32];                                             \
    float2 wn = (wb)[i * 96 + 64];                                             \
    aR[0][0] += ha.x * wr.x; aR[0][1] += ha.x * wr.y;                          \
    aR[1][0] += ha.y * wr.x; aR[1][1] += ha.y * wr.y;                          \
    aR[2][0] += hb.x * wr.x; aR[2][1] += hb.x * wr.y;                          \
    aR[3][0] += hb.y * wr.x; aR[3][1] += hb.y * wr.y;                          \
    aZ[0][0] += ha.x * wz.x; aZ[0][1] += ha.x * wz.y;                          \
    aZ[1][0] += ha.y * wz.x; aZ[1][1] += ha.y * wz.y;                          \
    aZ[2][0] += hb.x * wz.x; aZ[2][1] += hb.x * wz.y;                          \
    aZ[3][0] += hb.y * wz.x; aZ[3][1] += hb.y * wz.y;                          \
    aN[0][0] += ha.x * wn.x; aN[0][1] += ha.x * wn.y;                          \
    aN[1][0] += ha.y * wn.x; aN[1][1] += ha.y * wn.y;                          \
    aN[2][0] += hb.x * wn.x; aN[2][1] += hb.x * wn.y;                          \
    aN[3][0] += hb.y * wn.x; aN[3][1] += hb.y * wn.y;                          \
  }

// GRU nonlinearity + h update + h2 publish
#define GRU_FINISH(hp)                                                         \
  _Pragma("unroll")                                                            \
  for (int sl = 0; sl < 4; ++sl) {                                             \
    _Pragma("unroll")                                                          \
    for (int u = 0; u < 2; ++u) {                                              \
      float rg = sigf(aR[sl][u]);                                              \
      float zg = sigf(aZ[sl][u]);                                              \
      float ng = tanhf_(gN[sl][u] + rg * aN[sl][u]);                           \
      h[sl][u] = ng + zg * (h[sl][u] - ng);                                    \
    }                                                                          \
  }                                                                            \
  (hp)[lane]      = make_float2(h[0][0], h[1][0]);                             \
  (hp)[lane + 32] = make_float2(h[0][1], h[1][1]);                             \
  (hp)[64 + lane] = make_float2(h[2][0], h[3][0]);                             \
  (hp)[96 + lane] = make_float2(h[2][1], h[3][1]);                             \
  __syncwarp();

__global__ void __launch_bounds__(NTHR, 2) krnn_main(
    const float* __restrict__ X,
    const float* __restrict__ convw2, const float* __restrict__ convw3,
    const float* __restrict__ convw4, const float* __restrict__ convb,
    const float* __restrict__ enc_wih, const float* __restrict__ enc_whh,
    const float* __restrict__ enc_bih, const float* __restrict__ enc_bhh,
    const float* __restrict__ dec_wih, const float* __restrict__ dec_whh,
    const float* __restrict__ dec_bih, const float* __restrict__ dec_bhh,
    const float* __restrict__ lin_w, const float* __restrict__ lin_b)
{
  extern __shared__ char smraw[];
  Smem& sm = *reinterpret_cast<Smem*>(smraw);
  const int tid = threadIdx.x, lane = tid & 31, warp = tid >> 5;
  const int r = blockIdx.y;
  const int K = (r < 3) ? 2 : (r < 6 ? 3 : 4);
  const int rm = r - (r < 3 ? 0 : (r < 6 ? 3 : 6));
  const int D = (rm == 0) ? 1 : (rm == 1 ? 2 : 4);
  const int L = TIN - (K - 1) * D;
  const int seq0 = blockIdx.x * SPB;

  { // stage X slab (coalesced float4)
    const float4* xg = reinterpret_cast<const float4*>(X + (size_t)seq0 * (TIN * FIN));
    float4* xs4 = reinterpret_cast<float4*>(sm.xs);
    for (int i = tid; i < SPB * 30; i += NTHR) xs4[i] = xg[i];
  }
  { // conv weights / bias / linear weights
    const float* wsrc = (r < 3) ? convw2 + r * 128
                      : (r < 6) ? convw3 + (r - 3) * 192
                                : convw4 + (r - 6) * 256;
    for (int i = tid; i < 64 * K; i += NTHR) sm.cw[i] = wsrc[i];
    if (tid < 8) sm.cb[tid] = convb[r * 8 + tid];
    if (tid >= 32 && tid < 96) sm.lw[tid - 32] = lin_w[r * 64 + (tid - 32)];
  }
  { // encoder whh, transposed + gate-pair packed
    const float* W = enc_whh + r * (192 * 64);
    for (int idx = tid; idx < 6144; idx += NTHR) {
      int c = idx >> 6, i = idx & 63;
      int row = ((c >> 5) << 6) + (c & 31);
      sm.whh2[i * 96 + c] = make_float2(W[row * 64 + i], W[(row + 32) * 64 + i]);
    }
    const float* Wi = enc_wih + r * (192 * 8);
    for (int idx = tid; idx < 768; idx += NTHR) {
      int c = idx >> 3, f = idx & 7;
      int row = ((c >> 5) << 6) + (c & 31);
      sm.wih2[f * 96 + c] = make_float2(Wi[row * 8 + f], Wi[(row + 32) * 8 + f]);
    }
  }
  __syncthreads();

  { // dilated conv: thread -> (seq, cout)
    const int seq = tid >> 3, cout = tid & 7;
    const float* xr = sm.xs + seq * 120;
    const float* wr = sm.cw + cout * 8 * K;
    const float bias = sm.cb[cout];
    for (int l = 0; l < L; ++l) {
      float acc = bias;
      for (int k = 0; k < K; ++k) {
        const float* xk = xr + (l + k * D) * 8;
        #pragma unroll
        for (int ci = 0; ci < 8; ++ci) acc += xk[ci] * wr[ci * K + k];
      }
      sm.co[seq * 112 + cout * 14 + l] = acc;
    }
  }
  __syncthreads();

  const int sb = warp * 4;
  float2* hp = sm.h2 + (warp * 2) * 64;
  const float2* wb = sm.whh2 + lane;

  // encoder bias registers (rows: g*64 + lane + u*32)
  const float* ebi = enc_bih + r * 192;
  const float* ebh = enc_bhh + r * 192;
  const float cR0 = ebi[lane] + ebh[lane];
  const float cR1 = ebi[lane + 32] + ebh[lane + 32];
  const float cZ0 = ebi[64 + lane] + ebh[64 + lane];
  const float cZ1 = ebi[96 + lane] + ebh[96 + lane];
  const float biN0 = ebi[128 + lane], biN1 = ebi[160 + lane];
  const float bhN0 = ebh[128 + lane], bhN1 = ebh[160 + lane];

  float h[4][2];
  #pragma unroll
  for (int sl = 0; sl < 4; ++sl) { h[sl][0] = 0.f; h[sl][1] = 0.f; }
  hp[lane] = make_float2(0.f, 0.f); hp[lane + 32] = make_float2(0.f, 0.f);
  hp[64 + lane] = make_float2(0.f, 0.f); hp[96 + lane] = make_float2(0.f, 0.f);
  __syncwarp();

  // ----------------- encoder -----------------
  for (int t = 0; t < L; ++t) {
    float aR[4][2], aZ[4][2], aN[4][2], gN[4][2];
    #pragma unroll
    for (int sl = 0; sl < 4; ++sl) {
      aR[sl][0] = cR0; aR[sl][1] = cR1;
      aZ[sl][0] = cZ0; aZ[sl][1] = cZ1;
      aN[sl][0] = bhN0; aN[sl][1] = bhN1;
      gN[sl][0] = biN0; gN[sl][1] = biN1;
    }
    #pragma unroll
    for (int f = 0; f < 8; ++f) {
      float2 wr = sm.wih2[f * 96 + lane];
      float2 wz = sm.wih2[f * 96 + 32 + lane];
      float2 wn = sm.wih2[f * 96 + 64 + lane];
      #pragma unroll
      for (int sl = 0; sl < 4; ++sl) {
        float x = sm.co[(sb + sl) * 112 + f * 14 + t];
        aR[sl][0] += x * wr.x; aR[sl][1] += x * wr.y;
        aZ[sl][0] += x * wz.x; aZ[sl][1] += x * wz.y;
        gN[sl][0] += x * wn.x; gN[sl][1] += x * wn.y;
      }
    }
    GH_LOOP(hp, wb)
    GRU_FINISH(hp)
  }

  // ----------------- swap in decoder whh -----------------
  __syncthreads();
  {
    const float* W = dec_whh + r * (192 * 64);
    for (int idx = tid; idx < 6144; idx += NTHR) {
      int c = idx >> 6, i = idx & 63;
      int row = ((c >> 5) << 6) + (c & 31);
      sm.whh2[i * 96 + c] = make_float2(W[row * 64 + i], W[(row + 32) * 64 + i]);
    }
  }
  __syncthreads();

  const float* dbi = dec_bih + r * 192;
  const float* dbh = dec_bhh + r * 192;
  const float* dwi = dec_wih + r * 192;
  const float dR0 = dbi[lane] + dbh[lane];
  const float dR1 = dbi[lane + 32] + dbh[lane + 32];
  const float dZ0 = dbi[64 + lane] + dbh[64 + lane];
  const float dZ1 = dbi[96 + lane] + dbh[96 + lane];
  const float dbiN0 = dbi[128 + lane], dbiN1 = dbi[160 + lane];
  const float dbhN0 = dbh[128 + lane], dbhN1 = dbh[160 + lane];
  const float wR0 = dwi[lane], wR1 = dwi[lane + 32];
  const float wZ0 = dwi[64 + lane], wZ1 = dwi[96 + lane];
  const float wN0 = dwi[128 + lane], wN1 = dwi[160 + lane];
  const float lw0 = sm.lw[lane], lw1 = sm.lw[lane + 32];
  const float lb = lin_b[r];
  float lv[4];
  #pragma unroll
  for (int sl = 0; sl < 4; ++sl) lv[sl] = sm.xs[(sb + sl) * 120 + 112]; // X[s,14,0]

  // ----------------- decoder -----------------
  for (int t = 0; t < TOUT; ++t) {
    float aR[4][2], aZ[4][2], aN[4][2], gN[4][2];
    #pragma unroll
    for (int sl = 0; sl < 4; ++sl) {
      aR[sl][0] = dR0 + lv[sl] * wR0; aR[sl][1] = dR1 + lv[sl] * wR1;
      aZ[sl][0] = dZ0 + lv[sl] * wZ0; aZ[sl][1] = dZ1 + lv[sl] * wZ1;
      aN[sl][0] = dbhN0; aN[sl][1] = dbhN1;
      gN[sl][0] = dbiN0 + lv[sl] * wN0; gN[sl][1] = dbiN1 + lv[sl] * wN1;
    }
    GH_LOOP(hp, wb)
    GRU_FINISH(hp)
    // v = h @ lw + lb ; butterfly reduce over the 32 lanes (64 units)
    #pragma unroll
    for (int sl = 0; sl < 4; ++sl) {
      float p = h[sl][0] * lw0 + h[sl][1] * lw1;
      #pragma unroll
      for (int off = 16; off > 0; off >>= 1)
        p += __shfl_xor_sync(0xffffffffu, p, off);
      lv[sl] = p + lb;
    }
    if (lane == 0) {
      size_t base = ((size_t)r * BN_ + seq0 + sb) * TOUT + t;
      g_scratch[base]            = lv[0];
      g_scratch[base + TOUT]     = lv[1];
      g_scratch[base + 2 * TOUT] = lv[2];
      g_scratch[base + 3 * TOUT] = lv[3];
    }
  }
}

// softmax(embed) weighted combine over the 9 configs
__global__ void __launch_bounds__(256) krnn_combine(
    const float* __restrict__ embed, float* __restrict__ out)
{
  int idx = blockIdx.x * 256 + threadIdx.x;
  if (idx >= BN_ * TOUT) return;
  int s = idx / TOUT;
  int n = s % N_;
  float e[NCONF];
  float m = -1e30f;
  #pragma unroll
  for (int c = 0; c < NCONF; ++c) { e[c] = embed[n * NCONF + c]; m = fmaxf(m, e[c]); }
  float sum = 0.f;
  #pragma unroll
  for (int c = 0; c < NCONF; ++c) { e[c] = __expf(e[c] - m); sum += e[c]; }
  float acc = 0.f;
  #pragma unroll
  for (int c = 0; c < NCONF; ++c)
    acc += g_scratch[(size_t)c * (BN_ * TOUT) + idx] * e[c];
  out[idx] = acc / sum;
}

extern "C" void kernel_launch(void* const* d_in, const int* in_sizes, int n_in,
                              void* d_out, int out_size) {
  (void)in_sizes; (void)n_in; (void)out_size;
  const float* X    = (const float*)d_in[1];
  const float* cw2  = (const float*)d_in[2];
  const float* cw3  = (const float*)d_in[3];
  const float* cw4  = (const float*)d_in[4];
  const float* cb   = (const float*)d_in[5];
  const float* ewih = (const float*)d_in[6];
  const float* ewhh = (const float*)d_in[7];
  const float* ebih = (const float*)d_in[8];
  const float* ebhh = (const float*)d_in[9];
  const float* dwih = (const float*)d_in[10];
  const float* dwhh = (const float*)d_in[11];
  const float* dbih = (const float*)d_in[12];
  const float* dbhh = (const float*)d_in[13];
  const float* lw   = (const float*)d_in[14];
  const float* lb   = (const float*)d_in[15];
  const float* emb  = (const float*)d_in[16];

  cudaFuncSetAttribute(krnn_main, cudaFuncAttributeMaxDynamicSharedMemorySize,
                       (int)sizeof(Smem));
  dim3 grid(BN_ / SPB, NCONF);
  krnn_main<<<grid, NTHR, sizeof(Smem)>>>(X, cw2, cw3, cw4, cb, ewih, ewhh,
                                          ebih, ebhh, dwih, dwhh, dbih, dbhh,
                                          lw, lb);
  krnn_combine<<<(BN_ * TOUT + 255) / 256, 256>>>(emb, (float*)d_out);
}

// round 2
// speedup vs baseline: 1.0933x; 1.0933x over previous
#include <cuda_runtime.h>

// ---------------------------------------------------------------------------
// krnn_conv_local1: conv1d -> GRU encoder -> GRU decoder -> linear, x9 configs,
// softmax-combined. BN=51200 independent sequences; block = 32 sequences of one
// config, 4 warps x 8 sequences. Thread owns hidden-unit pair (lane, lane+32)
// packed in 64-bit regs; all GEMV work uses packed fma.rn.f32x2 (FFMA2).
// ---------------------------------------------------------------------------

namespace {
constexpr int B_ = 64, N_ = 800, TIN = 15, FIN = 8, TOUT = 12, NCONF = 9;
constexpr int BN_ = B_ * N_;          // 51200
constexpr int SPB = 32;               // sequences per block
constexpr int NTHR = 128;             // 4 warps, 8 seqs per warp
}

typedef unsigned long long u64;

// per-config outputs [NCONF][BN_][TOUT]
__device__ float g_scratch[(size_t)NCONF * BN_ * TOUT];

struct Smem {
  float2 whh2[64 * 96];   // [i][g*32+l] = (whh[g*64+l][i], whh[g*64+l+32][i])  48KB
  float2 wih2[8 * 96];    // [f][g*32+l] same packing, 192x8 input matrix
  float2 h2[16 * 64];     // [warp*4 + pair][i] = (h_seqEven[i], h_seqOdd[i])
  float  xs[SPB * 120];   // staged X slab (15*8 per seq)
  float  co[SPB * 112];   // conv output [seq][cout*14 + l]
  float  cw[256];         // conv weights [cout][cin][K]
  float  cb[8];
  float  lw[64];
};

__device__ __forceinline__ float sigf(float x) {
  return __fdividef(1.0f, 1.0f + __expf(-x));
}
__device__ __forceinline__ float tanhf_(float x) {
  return 1.0f - __fdividef(2.0f, __expf(2.0f * x) + 1.0f);
}

// packed f32x2 fma: d += a * b  (SASS FFMA2, 2 MACs per issue slot)
__device__ __forceinline__ void ffma2(u64& d, u64 a, u64 b) {
  asm("fma.rn.f32x2 %0, %1, %2, %0;" : "+l"(d) : "l"(a), "l"(b));
}
// broadcast scalar into both halves of an f32x2
__device__ __forceinline__ u64 b2(float x) {
  u64 r; asm("mov.b64 %0, {%1, %1};" : "=l"(r) : "f"(x)); return r;
}
__device__ __forceinline__ u64 pk2(float lo, float hi) {
  u64 r; asm("mov.b64 %0, {%1, %2};" : "=l"(r) : "f"(lo), "f"(hi)); return r;
}
__device__ __forceinline__ float2 up2(u64 v) {
  float2 f; asm("mov.b64 {%0, %1}, %2;" : "=f"(f.x), "=f"(f.y) : "l"(v)); return f;
}

__global__ void __launch_bounds__(NTHR, 2) krnn_main(
    const float* __restrict__ X,
    const float* __restrict__ convw2, const float* __restrict__ convw3,
    const float* __restrict__ convw4, const float* __restrict__ convb,
    const float* __restrict__ enc_wih, const float* __restrict__ enc_whh,
    const float* __restrict__ enc_bih, const float* __restrict__ enc_bhh,
    const float* __restrict__ dec_wih, const float* __restrict__ dec_whh,
    const float* __restrict__ dec_bih, const float* __restrict__ dec_bhh,
    const float* __restrict__ lin_w, const float* __restrict__ lin_b)
{
  extern __shared__ char smraw[];
  Smem& sm = *reinterpret_cast<Smem*>(smraw);
  const int tid = threadIdx.x, lane = tid & 31, warp = tid >> 5;
  const int r = blockIdx.y;
  const int K = (r < 3) ? 2 : (r < 6 ? 3 : 4);
  const int rm = r - (r < 3 ? 0 : (r < 6 ? 3 : 6));
  const int D = (rm == 0) ? 1 : (rm == 1 ? 2 : 4);
  const int L = TIN - (K - 1) * D;
  const int seq0 = blockIdx.x * SPB;

  { // stage X slab (coalesced float4)
    const float4* xg = reinterpret_cast<const float4*>(X + (size_t)seq0 * (TIN * FIN));
    float4* xs4 = reinterpret_cast<float4*>(sm.xs);
    for (int i = tid; i < SPB * 30; i += NTHR) xs4[i] = xg[i];
  }
  { // conv weights / bias / linear weights
    const float* wsrc = (r < 3) ? convw2 + r * 128
                      : (r < 6) ? convw3 + (r - 3) * 192
                                : convw4 + (r - 6) * 256;
    for (int i = tid; i < 64 * K; i += NTHR) sm.cw[i] = wsrc[i];
    if (tid < 8) sm.cb[tid] = convb[r * 8 + tid];
    if (tid >= 32 && tid < 96) sm.lw[tid - 32] = lin_w[r * 64 + (tid - 32)];
  }
  { // encoder whh, transposed + gate-pair packed
    const float* W = enc_whh + r * (192 * 64);
    for (int idx = tid; idx < 6144; idx += NTHR) {
      int c = idx >> 6, i = idx & 63;
      int row = ((c >> 5) << 6) + (c & 31);
      sm.whh2[i * 96 + c] = make_float2(W[row * 64 + i], W[(row + 32) * 64 + i]);
    }
    const float* Wi = enc_wih + r * (192 * 8);
    for (int idx = tid; idx < 768; idx += NTHR) {
      int c = idx >> 3, f = idx & 7;
      int row = ((c >> 5) << 6) + (c & 31);
      sm.wih2[f * 96 + c] = make_float2(Wi[row * 8 + f], Wi[(row + 32) * 8 + f]);
    }
  }
  __syncthreads();

  { // dilated conv: 256 (seq, cout) items over 128 threads
    for (int it = tid; it < 256; it += NTHR) {
      const int seq = it >> 3, cout = it & 7;
      const float* xr = sm.xs + seq * 120;
      const float* wr = sm.cw + cout * 8 * K;
      const float bias = sm.cb[cout];
      for (int l = 0; l < L; ++l) {
        float acc = bias;
        for (int k = 0; k < K; ++k) {
          const float* xk = xr + (l + k * D) * 8;
          #pragma unroll
          for (int ci = 0; ci < 8; ++ci) acc += xk[ci] * wr[ci * K + k];
        }
        sm.co[seq * 112 + cout * 14 + l] = acc;
      }
    }
  }
  __syncthreads();

  const int sb = warp * 8;
  float2* hp = sm.h2 + warp * 4 * 64;            // 4 pair-rows of 64
  const u64* wW = reinterpret_cast<const u64*>(sm.whh2) + lane;
  const u64* wI = reinterpret_cast<const u64*>(sm.wih2) + lane;

  // encoder bias pairs (rows g*64 + lane, g*64 + lane + 32)
  const float* ebi = enc_bih + r * 192;
  const float* ebh = enc_bhh + r * 192;
  const u64 cR  = pk2(ebi[lane] + ebh[lane],           ebi[lane + 32] + ebh[lane + 32]);
  const u64 cZ  = pk2(ebi[64 + lane] + ebh[64 + lane], ebi[96 + lane] + ebh[96 + lane]);
  const u64 biN = pk2(ebi[128 + lane], ebi[160 + lane]);
  const u64 bhN = pk2(ebh[128 + lane], ebh[160 + lane]);

  float h[8][2];
  #pragma unroll
  for (int s = 0; s < 8; ++s) { h[s][0] = 0.f; h[s][1] = 0.f; }
  for (int i = lane; i < 256; i += 32) hp[i] = make_float2(0.f, 0.f);
  __syncwarp();

#define GH_LOOP()                                                              \
  _Pragma("unroll 4")                                                          \
  for (int i = 0; i < 64; ++i) {                                               \
    u64 wr = wW[i * 96], wz = wW[i * 96 + 32], wn = wW[i * 96 + 64];           \
    float2 h01 = hp[i], h23 = hp[64 + i], h45 = hp[128 + i], h67 = hp[192 + i];\
    u64 b0 = b2(h01.x), b1 = b2(h01.y), b3 = b2(h23.x), b4 = b2(h23.y);        \
    u64 b5 = b2(h45.x), b6 = b2(h45.y), b7 = b2(h67.x), b8 = b2(h67.y);        \
    ffma2(aR[0], b0, wr); ffma2(aZ[0], b0, wz); ffma2(aN[0], b0, wn);          \
    ffma2(aR[1], b1, wr); ffma2(aZ[1], b1, wz); ffma2(aN[1], b1, wn);          \
    ffma2(aR[2], b3, wr); ffma2(aZ[2], b3, wz); ffma2(aN[2], b3, wn);          \
    ffma2(aR[3], b4, wr); ffma2(aZ[3], b4, wz); ffma2(aN[3], b4, wn);          \
    ffma2(aR[4], b5, wr); ffma2(aZ[4], b5, wz); ffma2(aN[4], b5, wn);          \
    ffma2(aR[5], b6, wr); ffma2(aZ[5], b6, wz); ffma2(aN[5], b6, wn);          \
    ffma2(aR[6], b7, wr); ffma2(aZ[6], b7, wz); ffma2(aN[6], b7, wn);          \
    ffma2(aR[7], b8, wr); ffma2(aZ[7], b8, wz); ffma2(aN[7], b8, wn);          \
  }

#define GRU_FINISH()                                                           \
  __syncwarp();                                                                \
  _Pragma("unroll")                                                            \
  for (int s = 0; s < 8; ++s) {                                                \
    float2 rr = up2(aR[s]), zz = up2(aZ[s]), nn = up2(aN[s]), gg = up2(gN[s]); \
    float r0 = sigf(rr.x), r1 = sigf(rr.y);                                    \
    float z0 = sigf(zz.x), z1 = sigf(zz.y);                                    \
    float n0 = tanhf_(gg.x + r0 * nn.x), n1 = tanhf_(gg.y + r1 * nn.y);        \
    h[s][0] = n0 + z0 * (h[s][0] - n0);                                        \
    h[s][1] = n1 + z1 * (h[s][1] - n1);                                        \
  }                                                                            \
  _Pragma("unroll")                                                            \
  for (int p = 0; p < 4; ++p) {                                                \
    hp[p * 64 + lane]      = make_float2(h[2 * p][0], h[2 * p + 1][0]);        \
    hp[p * 64 + lane + 32] = make_float2(h[2 * p][1], h[2 * p + 1][1]);        \
  }                                                                            \
  __syncwarp();

  // ----------------- encoder -----------------
  for (int t = 0; t < L; ++t) {
    u64 aR[8], aZ[8], aN[8], gN[8];
    #pragma unroll
    for (int s = 0; s < 8; ++s) { aR[s] = cR; aZ[s] = cZ; aN[s] = bhN; gN[s] = biN; }
    #pragma unroll
    for (int f = 0; f < 8; ++f) {
      u64 wr = wI[f * 96], wz = wI[f * 96 + 32], wn = wI[f * 96 + 64];
      #pragma unroll
      for (int s = 0; s < 8; ++s) {
        u64 xb = b2(sm.co[(sb + s) * 112 + f * 14 + t]);
        ffma2(aR[s], xb, wr); ffma2(aZ[s], xb, wz); ffma2(gN[s], xb, wn);
      }
    }
    GH_LOOP()
    GRU_FINISH()
  }

  // ----------------- swap in decoder whh -----------------
  __syncthreads();
  {
    const float* W = dec_whh + r * (192 * 64);
    for (int idx = tid; idx < 6144; idx += NTHR) {
      int c = idx >> 6, i = idx & 63;
      int row = ((c >> 5) << 6) + (c & 31);
      sm.whh2[i * 96 + c] = make_float2(W[row * 64 + i], W[(row + 32) * 64 + i]);
    }
  }
  __syncthreads();

  const float* dbi = dec_bih + r * 192;
  const float* dbh = dec_bhh + r * 192;
  const float* dwi = dec_wih + r * 192;
  const u64 dR  = pk2(dbi[lane] + dbh[lane],           dbi[lane + 32] + dbh[lane + 32]);
  const u64 dZ  = pk2(dbi[64 + lane] + dbh[64 + lane], dbi[96 + lane] + dbh[96 + lane]);
  const u64 dbiN = pk2(dbi[128 + lane], dbi[160 + lane]);
  const u64 dbhN = pk2(dbh[128 + lane], dbh[160 + lane]);
  const u64 wiR = pk2(dwi[lane],       dwi[lane + 32]);
  const u64 wiZ = pk2(dwi[64 + lane],  dwi[96 + lane]);
  const u64 wiN = pk2(dwi[128 + lane], dwi[160 + lane]);
  const float lw0 = sm.lw[lane], lw1 = sm.lw[lane + 32];
  const float lb = lin_b[r];
  float lv[8];
  #pragma unroll
  for (int s = 0; s < 8; ++s) lv[s] = sm.xs[(sb + s) * 120 + 112]; // X[s,14,0]

  // ----------------- decoder -----------------
  for (int t = 0; t < TOUT; ++t) {
    u64 aR[8], aZ[8], aN[8], gN[8];
    #pragma unroll
    for (int s = 0; s < 8; ++s) {
      u64 xb = b2(lv[s]);
      aR[s] = dR;   ffma2(aR[s], xb, wiR);
      aZ[s] = dZ;   ffma2(aZ[s], xb, wiZ);
      gN[s] = dbiN; ffma2(gN[s], xb, wiN);
      aN[s] = dbhN;
    }
    GH_LOOP()
    GRU_FINISH()
    // v = h @ lw + lb ; butterfly reduce over 32 lanes (64 units)
    #pragma unroll
    for (int s = 0; s < 8; ++s) {
      float p = h[s][0] * lw0 + h[s][1] * lw1;
      #pragma unroll
      for (int off = 16; off > 0; off >>= 1)
        p += __shfl_xor_sync(0xffffffffu, p, off);
      lv[s] = p + lb;
    }
    if (lane == 0) {
      size_t base = ((size_t)r * BN_ + seq0 + sb) * TOUT + t;
      #pragma unroll
      for (int s = 0; s < 8; ++s) g_scratch[base + (size_t)s * TOUT] = lv[s];
    }
  }
}

// softmax(embed) weighted combine over the 9 configs
__global__ void __launch_bounds__(256) krnn_combine(
    const float* __restrict__ embed, float* __restrict__ out)
{
  int idx = blockIdx.x * 256 + threadIdx.x;
  if (idx >= BN_ * TOUT) return;
  int s = idx / TOUT;
  int n = s % N_;
  float e[NCONF];
  float m = -1e30f;
  #pragma unroll
  for (int c = 0; c < NCONF; ++c) { e[c] = embed[n * NCONF + c]; m = fmaxf(m, e[c]); }
  float sum = 0.f;
  #pragma unroll
  for (int c = 0; c < NCONF; ++c) { e[c] = __expf(e[c] - m); sum += e[c]; }
  float acc = 0.f;
  #pragma unroll
  for (int c = 0; c < NCONF; ++c)
    acc += g_scratch[(size_t)c * (BN_ * TOUT) + idx] * e[c];
  out[idx] = acc / sum;
}

extern "C" void kernel_launch(void* const* d_in, const int* in_sizes, int n_in,
                              void* d_out, int out_size) {
  (void)in_sizes; (void)n_in; (void)out_size;
  const float* X    = (const float*)d_in[1];
  const float* cw2  = (const float*)d_in[2];
  const float* cw3  = (const float*)d_in[3];
  const float* cw4  = (const float*)d_in[4];
  const float* cb   = (const float*)d_in[5];
  const float* ewih = (const float*)d_in[6];
  const float* ewhh = (const float*)d_in[7];
  const float* ebih = (const float*)d_in[8];
  const float* ebhh = (const float*)d_in[9];
  const float* dwih = (const float*)d_in[10];
  const float* dwhh = (const float*)d_in[11];
  const float* dbih = (const float*)d_in[12];
  const float* dbhh = (const float*)d_in[13];
  const float* lw   = (const float*)d_in[14];
  const float* lb   = (const float*)d_in[15];
  const float* emb  = (const float*)d_in[16];

  cudaFuncSetAttribute(krnn_main, cudaFuncAttributeMaxDynamicSharedMemorySize,
                       (int)sizeof(Smem));
  dim3 grid(BN_ / SPB, NCONF);
  krnn_main<<<grid, NTHR, sizeof(Smem)>>>(X, cw2, cw3, cw4, cb, ewih, ewhh,
                                          ebih, ebhh, dwih, dwhh, dbih, dbhh,
                                          lw, lb);
  krnn_combine<<<(BN_ * TOUT + 255) / 256, 256>>>(emb, (float*)d_out);
}

// round 5
// speedup vs baseline: 1.1409x; 1.0436x over previous
#include <cuda_runtime.h>
#include <cuda_bf16.h>
#include <cstdint>

// ---------------------------------------------------------------------------
// krnn_conv_local1 via mma.sync.m16n8k16 (bf16, f32 accum), bf16x2 split for
// ~fp32 accuracy. Block = 128 seqs of one config, 256 threads (8 warps).
// Per GRU step: D[128x256] = A[128xK] @ B^T, N blocks {r, z, hn, in}.
//   A smem: [h_hi(4 t) | h_lo(4 t) | x-tiles(2)]  (k16-tiles, pair-permuted)
//   B smem: [Wh_hi | Wh_lo | [Wx_hi|Wx_hi] | [Wx_lo|0]] per gate row
// 3-term split GEMM: hi*hi + lo*hi + hi*lo. Accums live in mma registers.
// ---------------------------------------------------------------------------

namespace {
constexpr int B_ = 64, N_ = 800, TOUT = 12, NCONF = 9;
constexpr int BN_ = B_ * N_;           // 51200
constexpr int SPB = 128;
constexpr int NTHR = 256;
constexpr int NBLK = BN_ / SPB;        // 400

constexpr int AST = 168;               // bf16 stride (160 used + pad)
constexpr int BST = 168;
constexpr int OFF_A  = 0;
constexpr int A_BYTES = SPB * AST * 2;         // 43008
constexpr int OFF_B  = OFF_A + A_BYTES;
constexpr int B_BYTES = 256 * BST * 2;         // 86016
constexpr int OFF_CO = OFF_B + B_BYTES;
constexpr int CO_BYTES = SPB * 113 * 4;        // 57856
constexpr int OFF_LVP = OFF_CO + CO_BYTES;
constexpr int LVP_BYTES = SPB * 4 * 4;
constexpr int SMEM_TOTAL = OFF_LVP + LVP_BYTES + 256;   // ~189KB

// within-16 pair permutation: position of original col c
__host__ __device__ __forceinline__ constexpr int posf(int c) {
  return ((c & 6) >> 1) * 4 + (c & 1) + ((c & 8) >> 3) * 2;
}
}

__device__ float g_scratch[(size_t)NCONF * BN_ * TOUT];

__device__ __forceinline__ float sigf(float x) {
  return __fdividef(1.0f, 1.0f + __expf(-x));
}
__device__ __forceinline__ float tanhf_(float x) {
  return 1.0f - __fdividef(2.0f, __expf(2.0f * x) + 1.0f);
}
__device__ __forceinline__ uint32_t pack2(float a, float b) {
  __nv_bfloat162 p = __floats2bfloat162_rn(a, b);
  return *reinterpret_cast<uint32_t*>(&p);
}
__device__ __forceinline__ void split2(float v, __nv_bfloat16& h, __nv_bfloat16& l) {
  h = __float2bfloat16_rn(v);
  l = __float2bfloat16_rn(v - __bfloat162float(h));
}
__device__ __forceinline__ uint32_t packsplit_hi(float a, float b) {
  return pack2(a, b);  // rn-rounded hi parts
}
__device__ __forceinline__ uint32_t packsplit_lo(float a, float b) {
  __nv_bfloat16 ha = __float2bfloat16_rn(a), hb = __float2bfloat16_rn(b);
  return pack2(a - __bfloat162float(ha), b - __bfloat162float(hb));
}

__device__ __forceinline__ void mma_bf16(float* d, uint32_t a0, uint32_t a1,
                                         uint32_t a2, uint32_t a3,
                                         uint32_t b0, uint32_t b1) {
  asm volatile(
    "mma.sync.aligned.m16n8k16.row.col.f32.bf16.bf16.f32 "
    "{%0,%1,%2,%3}, {%4,%5,%6,%7}, {%8,%9}, {%0,%1,%2,%3};"
    : "+f"(d[0]), "+f"(d[1]), "+f"(d[2]), "+f"(d[3])
    : "r"(a0), "r"(a1), "r"(a2), "r"(a3), "r"(b0), "r"(b1));
}

// Build B [256 rows x 160 cols bf16, pair-permuted] for enc (fin=8) or dec (fin=1)
__device__ void build_B(__nv_bfloat16* Bp, int tid,
                        const float* whh, const float* wih, int fin) {
  for (int idx = tid; idx < 256 * 160; idx += NTHR) {
    int n = idx / 160, col = idx - n * 160;
    int kt = col >> 4, p = col & 15;
    int c = ((p >> 2) << 1) + (p & 1) + ((p & 2) << 2);   // inverse perm
    int g = n >> 6, j = n & 63;
    __nv_bfloat16 out = __float2bfloat16_rn(0.f);
    if (kt < 8) {                       // h part
      if (g != 3) {
        int k = (kt & 3) * 16 + c;
        float v = whh[(g * 64 + j) * 64 + k];
        __nv_bfloat16 hi, lo; split2(v, hi, lo);
        out = (kt < 4) ? hi : lo;
      }
    } else if (kt == 8) {               // [Wx_hi | Wx_hi] duplicated
      int f = c & 7;
      if (g != 2 && f < fin) {
        int row = (g == 3 ? 128 : g * 64) + j;
        float v = wih[row * fin + f];
        __nv_bfloat16 hi, lo; split2(v, hi, lo);
        out = hi;
      }
    } else {                            // kt==9: [Wx_lo | 0]
      if (g != 2 && c < fin) {
        int row = (g == 3 ? 128 : g * 64) + j;
        float v = wih[row * fin + c];
        __nv_bfloat16 hi, lo; split2(v, hi, lo);
        out = lo;
      }
    }
    Bp[n * BST + col] = out;
  }
}

__global__ void __launch_bounds__(NTHR, 1) krnn_mma(
    const float* __restrict__ X,
    const float* __restrict__ convw2, const float* __restrict__ convw3,
    const float* __restrict__ convw4, const float* __restrict__ convb,
    const float* __restrict__ enc_wih, const float* __restrict__ enc_whh,
    const float* __restrict__ enc_bih, const float* __restrict__ enc_bhh,
    const float* __restrict__ dec_wih, const float* __restrict__ dec_whh,
    const float* __restrict__ dec_bih, const float* __restrict__ dec_bhh,
    const float* __restrict__ lin_w, const float* __restrict__ lin_b)
{
  extern __shared__ char smraw[];
  __nv_bfloat16* Asm = reinterpret_cast<__nv_bfloat16*>(smraw + OFF_A);
  __nv_bfloat16* Bsm = reinterpret_cast<__nv_bfloat16*>(smraw + OFF_B);
  float* co  = reinterpret_cast<float*>(smraw + OFF_CO);
  float* lvp = reinterpret_cast<float*>(smraw + OFF_LVP);

  const int tid = threadIdx.x, lane = tid & 31, warp = tid >> 5;
  const int g = lane >> 2, t = lane & 3;
  const int mh = warp >> 2, ng = warp & 3;
  const int r = blockIdx.x % NCONF;
  const int blk = blockIdx.x / NCONF;
  const int seq0 = blk * SPB;
  const int K = (r < 3) ? 2 : (r < 6 ? 3 : 4);
  const int rm = r - (r < 3 ? 0 : (r < 6 ? 3 : 6));
  const int D = (rm == 0) ? 1 : (rm == 1 ? 2 : 4);
  const int L = 15 - (K - 1) * D;

  // ---- stage X into B region (temp) ----
  {
    const float4* xg = reinterpret_cast<const float4*>(X + (size_t)seq0 * 120);
    float4* xs4 = reinterpret_cast<float4*>(smraw + OFF_B);
    for (int i = tid; i < SPB * 30; i += NTHR) xs4[i] = xg[i];
  }
  __syncthreads();

  // ---- conv (reads X temp, writes co) ----
  {
    const float* xs = reinterpret_cast<const float*>(smraw + OFF_B);
    const float* wsrc = (r < 3) ? convw2 + r * 128
                      : (r < 6) ? convw3 + (r - 3) * 192
                                : convw4 + (r - 6) * 256;
    for (int it = tid; it < SPB * 8; it += NTHR) {
      int seq = it >> 3, f = it & 7;
      const float* xr = xs + seq * 120;
      const float* wr = wsrc + f * 8 * K;
      float bias = convb[r * 8 + f];
      for (int l = 0; l < L; ++l) {
        float acc = bias;
        for (int k = 0; k < K; ++k) {
          const float* xk = xr + (l + k * D) * 8;
          #pragma unroll
          for (int ci = 0; ci < 8; ++ci) acc += xk[ci] * wr[ci * K + k];
        }
        co[seq * 113 + f * 14 + l] = acc;
      }
    }
  }
  __syncthreads();

  // ---- build encoder B (overwrites X temp) ----
  build_B(Bsm, tid, enc_whh + r * 192 * 64, enc_wih + r * 192 * 8, 8);

  // ---- zero A ----
  {
    uint32_t* a4 = reinterpret_cast<uint32_t*>(Asm);
    for (int i = tid; i < SPB * AST / 2; i += NTHR) a4[i] = 0;
  }
  __syncthreads();

  // ---- stage x(step) helper (as lambda) ----
  auto stage_x = [&](int step) {
    int row = tid >> 1, half = tid & 1;
    __nv_bfloat16* Ar = Asm + row * AST;
    #pragma unroll
    for (int pp = 0; pp < 2; ++pp) {
      int f0 = half * 4 + pp * 2;
      float v0 = co[row * 113 + f0 * 14 + step];
      float v1 = co[row * 113 + (f0 + 1) * 14 + step];
      int ph = posf(f0);
      *reinterpret_cast<uint32_t*>(Ar + 128 + ph)     = packsplit_hi(v0, v1);
      *reinterpret_cast<uint32_t*>(Ar + 128 + ph + 2) = packsplit_lo(v0, v1);
      *reinterpret_cast<uint32_t*>(Ar + 144 + ph)     = packsplit_hi(v0, v1);
    }
  };
  stage_x(0);

  // ---- biases (encoder) ----
  float bR[2][2], bZ[2][2], bHn[2][2], bIn[2][2], lwr[2][2];
  {
    const float* bi = enc_bih + r * 192;
    const float* bh = enc_bhh + r * 192;
    #pragma unroll
    for (int j = 0; j < 2; ++j)
      #pragma unroll
      for (int k = 0; k < 2; ++k) {
        int u = 16 * ng + 8 * j + 2 * t + k;
        bR[j][k]  = bi[u] + bh[u];
        bZ[j][k]  = bi[64 + u] + bh[64 + u];
        bHn[j][k] = bh[128 + u];
        bIn[j][k] = bi[128 + u];
      }
  }

  float h_[4][2][2][2];
  #pragma unroll
  for (int m = 0; m < 4; ++m)
    #pragma unroll
    for (int hh = 0; hh < 2; ++hh)
      #pragma unroll
      for (int j = 0; j < 2; ++j) { h_[m][hh][j][0] = 0.f; h_[m][hh][j][1] = 0.f; }

  const int nsteps = L + TOUT;
  const float lbv = lin_b[r];

  for (int step = 0; step < nsteps; ++step) {
    __syncthreads();   // A (h + x) ready, B ready

    // -------- GEMM: 3-term split + x terms --------
    float acc[4][8][4];
    #pragma unroll
    for (int m = 0; m < 4; ++m)
      #pragma unroll
      for (int s = 0; s < 8; ++s)
        #pragma unroll
        for (int c = 0; c < 4; ++c) acc[m][s][c] = 0.f;

    const int kopA[14] = {0,1,2,3, 4,5,6,7, 0,1,2,3, 8,9};
    const int kopB[14] = {0,1,2,3, 0,1,2,3, 4,5,6,7, 8,9};
    #pragma unroll
    for (int kop = 0; kop < 14; ++kop) {
      const int ka = kopA[kop], kb = kopB[kop];
      uint2 av0[4], av1[4];
      #pragma unroll
      for (int m = 0; m < 4; ++m) {
        int row = 64 * mh + 16 * m + g;
        av0[m] = *reinterpret_cast<const uint2*>(Asm + row * AST + ka * 16 + 4 * t);
        av1[m] = *reinterpret_cast<const uint2*>(Asm + (row + 8) * AST + ka * 16 + 4 * t);
      }
      #pragma unroll
      for (int s = 0; s < 8; ++s) {
        const bool use = (kop < 12) ? (s < 6) : (s < 4 || s >= 6);
        if (use) {
          int n0 = (s >> 1) * 64 + 16 * ng + 8 * (s & 1);
          uint2 bv = *reinterpret_cast<const uint2*>(Bsm + (n0 + g) * BST + kb * 16 + 4 * t);
          #pragma unroll
          for (int m = 0; m < 4; ++m)
            mma_bf16(acc[m][s], av0[m].x, av1[m].x, av0[m].y, av1[m].y, bv.x, bv.y);
        }
      }
    }
    __syncthreads();   // all smem reads done; safe to overwrite A

    // -------- epilogue: GRU update (registers only) --------
    #pragma unroll
    for (int m = 0; m < 4; ++m)
      #pragma unroll
      for (int hh = 0; hh < 2; ++hh)
        #pragma unroll
        for (int j = 0; j < 2; ++j)
          #pragma unroll
          for (int k = 0; k < 2; ++k) {
            int c = 2 * hh + k;
            float R = sigf(acc[m][0 + j][c] + bR[j][k]);
            float Z = sigf(acc[m][2 + j][c] + bZ[j][k]);
            float Nn = tanhf_(acc[m][6 + j][c] + bIn[j][k]
                              + R * (acc[m][4 + j][c] + bHn[j][k]));
            float& H = h_[m][hh][j][k];
            H = Nn + Z * (H - Nn);
          }

    // write h (hi/lo bf16) back to A
    #pragma unroll
    for (int m = 0; m < 4; ++m)
      #pragma unroll
      for (int hh = 0; hh < 2; ++hh) {
        int row = 64 * mh + 16 * m + 8 * hh + g;
        __nv_bfloat16* Ar = Asm + row * AST;
        #pragma unroll
        for (int j = 0; j < 2; ++j) {
          int u2 = 16 * ng + 8 * j + 2 * t;
          int hipos = (u2 >> 4) * 16 + posf(u2 & 15);
          float v0 = h_[m][hh][j][0], v1 = h_[m][hh][j][1];
          *reinterpret_cast<uint32_t*>(Ar + hipos)      = packsplit_hi(v0, v1);
          *reinterpret_cast<uint32_t*>(Ar + hipos + 64) = packsplit_lo(v0, v1);
        }
      }

    if (step < L - 1) {
      stage_x(step + 1);
    } else if (step == L - 1) {
      // ---- transition to decoder ----
      build_B(Bsm, tid, dec_whh + r * 192 * 64, dec_wih + r * 192, 1);
      // zero x tiles (cols 128..159) and stage lv0
      for (int i = tid; i < SPB * 16; i += NTHR) {
        int row = i >> 4;
        reinterpret_cast<uint32_t*>(Asm + row * AST + 128)[i & 15] = 0;
      }
      __syncthreads();
      if (tid < SPB) {
        float lv = X[(size_t)(seq0 + tid) * 120 + 112];
        __nv_bfloat16* Ar = Asm + tid * AST;
        *reinterpret_cast<uint32_t*>(Ar + 128) = packsplit_hi(lv, 0.f);
        *reinterpret_cast<uint32_t*>(Ar + 130) = packsplit_lo(lv, 0.f);
        *reinterpret_cast<uint32_t*>(Ar + 144) = packsplit_hi(lv, 0.f);
      }
      // decoder biases + lin_w
      const float* bi = dec_bih + r * 192;
      const float* bh = dec_bhh + r * 192;
      #pragma unroll
      for (int j = 0; j < 2; ++j)
        #pragma unroll
        for (int k = 0; k < 2; ++k) {
          int u = 16 * ng + 8 * j + 2 * t + k;
          bR[j][k]  = bi[u] + bh[u];
          bZ[j][k]  = bi[64 + u] + bh[64 + u];
          bHn[j][k] = bh[128 + u];
          bIn[j][k] = bi[128 + u];
          lwr[j][k] = lin_w[r * 64 + u];
        }
    } else {
      // ---- decoder: lv = h @ lw + lb ----
      #pragma unroll
      for (int m = 0; m < 4; ++m)
        #pragma unroll
        for (int hh = 0; hh < 2; ++hh) {
          float p = h_[m][hh][0][0] * lwr[0][0] + h_[m][hh][0][1] * lwr[0][1]
                  + h_[m][hh][1][0] * lwr[1][0] + h_[m][hh][1][1] * lwr[1][1];
          p += __shfl_xor_sync(0xffffffffu, p, 1);
          p += __shfl_xor_sync(0xffffffffu, p, 2);
          if (t == 0) lvp[(64 * mh + 16 * m + 8 * hh + g) * 4 + ng] = p;
        }
      __syncthreads();
      if (tid < SPB) {
        float lv = lvp[tid * 4] + lvp[tid * 4 + 1] + lvp[tid * 4 + 2]
                 + lvp[tid * 4 + 3] + lbv;
        __nv_bfloat16* Ar = Asm + tid * AST;
        *reinterpret_cast<uint32_t*>(Ar + 128) = packsplit_hi(lv, 0.f);
        *reinterpret_cast<uint32_t*>(Ar + 130) = packsplit_lo(lv, 0.f);
        *reinterpret_cast<uint32_t*>(Ar + 144) = packsplit_hi(lv, 0.f);
        g_scratch[((size_t)r * BN_ + seq0 + tid) * TOUT + (step - L)] = lv;
      }
    }
  }
}

// softmax(embed) weighted combine over the 9 configs
__global__ void __launch_bounds__(256) krnn_combine(
    const float* __restrict__ embed, float* __restrict__ out)
{
  int idx = blockIdx.x * 256 + threadIdx.x;
  if (idx >= BN_ * TOUT) return;
  int s = idx / TOUT;
  int n = s % N_;
  float e[NCONF];
  float m = -1e30f;
  #pragma unroll
  for (int c = 0; c < NCONF; ++c) { e[c] = embed[n * NCONF + c]; m = fmaxf(m, e[c]); }
  float sum = 0.f;
  #pragma unroll
  for (int c = 0; c < NCONF; ++c) { e[c] = __expf(e[c] - m); sum += e[c]; }
  float acc = 0.f;
  #pragma unroll
  for (int c = 0; c < NCONF; ++c)
    acc += g_scratch[(size_t)c * (BN_ * TOUT) + idx] * e[c];
  out[idx] = acc / sum;
}

extern "C" void kernel_launch(void* const* d_in, const int* in_sizes, int n_in,
                              void* d_out, int out_size) {
  (void)in_sizes; (void)n_in; (void)out_size;
  const float* X    = (const float*)d_in[1];
  const float* cw2  = (const float*)d_in[2];
  const float* cw3  = (const float*)d_in[3];
  const float* cw4  = (const float*)d_in[4];
  const float* cb   = (const float*)d_in[5];
  const float* ewih = (const float*)d_in[6];
  const float* ewhh = (const float*)d_in[7];
  const float* ebih = (const float*)d_in[8];
  const float* ebhh = (const float*)d_in[9];
  const float* dwih = (const float*)d_in[10];
  const float* dwhh = (const float*)d_in[11];
  const float* dbih = (const float*)d_in[12];
  const float* dbhh = (const float*)d_in[13];
  const float* lw   = (const float*)d_in[14];
  const float* lb   = (const float*)d_in[15];
  const float* emb  = (const float*)d_in[16];

  cudaFuncSetAttribute(krnn_mma, cudaFuncAttributeMaxDynamicSharedMemorySize,
                       SMEM_TOTAL);
  krnn_mma<<<NBLK * NCONF, NTHR, SMEM_TOTAL>>>(X, cw2, cw3, cw4, cb, ewih, ewhh,
                                               ebih, ebhh, dwih, dwhh, dbih,
                                               dbhh, lw, lb);
  krnn_combine<<<(BN_ * TOUT + 255) / 256, 256>>>(emb, (float*)d_out);
}